// round 2
// baseline (speedup 1.0000x reference)
#include <cuda_runtime.h>

// Problem constants
constexpr int GM = 32768;          // B*S rows
constexpr int GK = 1024;           // F
constexpr int GN = 1024;           // F
constexpr int ATT_SIZE = 33554432; // B*S*F
constexpr int NBH = 64;            // B*H
constexpr int NSLAB = 8192;        // rows per head slab
constexpr int NCHUNK = 32;         // row chunks per slab for P accumulation

// Scratch (device globals; allocation is forbidden)
__device__ float g_Qp[GM * GN];
__device__ float g_Kp[GM * GN];
__device__ float g_Vp[GM * GN];
__device__ float g_Ppart[NBH * NCHUNK * 4096];

// ---------------- packed f32x2 helpers (sm_100+ PTX) ----------------
__device__ __forceinline__ unsigned long long pk2(float x, float y) {
    unsigned long long r;
    asm("mov.b64 %0, {%1, %2};" : "=l"(r) : "f"(x), "f"(y));
    return r;
}
__device__ __forceinline__ unsigned long long ff2(unsigned long long a,
                                                  unsigned long long b,
                                                  unsigned long long c) {
    unsigned long long d;
    asm("fma.rn.f32x2 %0, %1, %2, %3;" : "=l"(d) : "l"(a), "l"(b), "l"(c));
    return d;
}
__device__ __forceinline__ float f2lo(unsigned long long v) {
    return __uint_as_float((unsigned)(v & 0xffffffffull));
}
__device__ __forceinline__ float f2hi(unsigned long long v) {
    return __uint_as_float((unsigned)(v >> 32));
}

// ---------------- GEMM: C = A(GMxGK) * B(GKxGN), all row-major -------
// 128x128 block tile, 8x8 per thread, BK=8, double-buffered smem,
// inner product via packed fma.rn.f32x2 (2 FMA/instr to beat the
// half-rate 3-reg FFMA on sm_103a).
__global__ __launch_bounds__(256, 2) void gemm_f32(const float* __restrict__ A,
                                                   const float* __restrict__ Bm,
                                                   int which) {
    float* C = (which == 0) ? g_Qp : (which == 1) ? g_Kp : g_Vp;

    __shared__ float As[2][8][132];   // [k][m], padded to kill store conflicts
    __shared__ float Bs[2][8][128];   // [k][n]

    const int tid  = threadIdx.x;
    const int arow = tid >> 1;           // 0..127
    const int acol = (tid & 1) << 2;     // 0 or 4
    const int brow = tid >> 5;           // 0..7
    const int bcol = (tid & 31) << 2;    // 0..124
    const int tx4  = (tid & 15) << 2;    // 0..60
    const int ty4  = (tid >> 4) << 2;    // 0..60

    const float* Ab = A + (size_t)blockIdx.y * 128 * GK;
    const float* Bb = Bm + (size_t)blockIdx.x * 128;

    unsigned long long acc[8][4];
#pragma unroll
    for (int i = 0; i < 8; i++)
#pragma unroll
        for (int j = 0; j < 4; j++) acc[i][j] = 0ull;

    // prologue: tile 0 -> buffer 0
    {
        float4 av = *(const float4*)(Ab + (size_t)arow * GK + acol);
        float4 bv = *(const float4*)(Bb + (size_t)brow * GN + bcol);
        As[0][acol + 0][arow] = av.x;
        As[0][acol + 1][arow] = av.y;
        As[0][acol + 2][arow] = av.z;
        As[0][acol + 3][arow] = av.w;
        *(float4*)&Bs[0][brow][bcol] = bv;
    }
    __syncthreads();

#pragma unroll 1
    for (int kt = 0; kt < GK / 8; kt++) {
        const int cur = kt & 1;
        float4 av2, bv2;
        if (kt < GK / 8 - 1) {
            av2 = *(const float4*)(Ab + (size_t)arow * GK + (kt + 1) * 8 + acol);
            bv2 = *(const float4*)(Bb + (size_t)((kt + 1) * 8 + brow) * GN + bcol);
        }
#pragma unroll
        for (int k = 0; k < 8; k++) {
            float4 a0 = *(const float4*)&As[cur][k][ty4];
            float4 a1 = *(const float4*)&As[cur][k][64 + ty4];
            ulonglong2 b0 = *(const ulonglong2*)&Bs[cur][k][tx4];
            ulonglong2 b1 = *(const ulonglong2*)&Bs[cur][k][64 + tx4];
            unsigned long long bb[4] = {b0.x, b0.y, b1.x, b1.y};
            float ar[8] = {a0.x, a0.y, a0.z, a0.w, a1.x, a1.y, a1.z, a1.w};
#pragma unroll
            for (int i = 0; i < 8; i++) {
                unsigned long long aa = pk2(ar[i], ar[i]);
#pragma unroll
                for (int j = 0; j < 4; j++) acc[i][j] = ff2(aa, bb[j], acc[i][j]);
            }
        }
        if (kt < GK / 8 - 1) {
            const int nxt = cur ^ 1;
            As[nxt][acol + 0][arow] = av2.x;
            As[nxt][acol + 1][arow] = av2.y;
            As[nxt][acol + 2][arow] = av2.z;
            As[nxt][acol + 3][arow] = av2.w;
            *(float4*)&Bs[nxt][brow][bcol] = bv2;
        }
        __syncthreads();
    }

    float* Cb = C + (size_t)(blockIdx.y * 128) * GN + blockIdx.x * 128;
#pragma unroll
    for (int i = 0; i < 8; i++) {
        int m = (i < 4) ? (ty4 + i) : (64 + ty4 + (i - 4));
        float4 v0 = make_float4(f2lo(acc[i][0]), f2hi(acc[i][0]),
                                f2lo(acc[i][1]), f2hi(acc[i][1]));
        float4 v1 = make_float4(f2lo(acc[i][2]), f2hi(acc[i][2]),
                                f2lo(acc[i][3]), f2hi(acc[i][3]));
        *(float4*)(Cb + (size_t)m * GN + tx4) = v0;
        *(float4*)(Cb + (size_t)m * GN + 64 + tx4) = v1;
    }
}

// ------------- LayerNorm(K), LayerNorm(V), partial P = Kn^T Vn -------------
// grid: (NCHUNK, NBH). Each block: 256 rows of the (8192 x 64) head slab,
// processed in 4 tiles of 64 rows. LN is exact per 64-wide row (biased var).
__global__ __launch_bounds__(256) void ln_pkv_kernel(const float* __restrict__ lnks,
                                                     const float* __restrict__ lnkb,
                                                     const float* __restrict__ lnvs,
                                                     const float* __restrict__ lnvb) {
    __shared__ float Ks[64][64];
    __shared__ float Vs[64][64];

    const int bh = blockIdx.y;
    const int chunk = blockIdx.x;
    const int h = bh & 15;

    const float* Kslab = g_Kp + (size_t)bh * (NSLAB * 64) + (size_t)chunk * 256 * 64;
    const float* Vslab = g_Vp + (size_t)bh * (NSLAB * 64) + (size_t)chunk * 256 * 64;

    const int tid = threadIdx.x;
    const int lane = tid & 31;
    const int warp = tid >> 5;
    const int tx = tid & 15;
    const int ty = tid >> 4;

    // per-lane LN params (cols 2*lane, 2*lane+1)
    const float ks0 = lnks[h * 64 + 2 * lane], ks1 = lnks[h * 64 + 2 * lane + 1];
    const float kb0 = lnkb[h * 64 + 2 * lane], kb1 = lnkb[h * 64 + 2 * lane + 1];
    const float vs0 = lnvs[h * 64 + 2 * lane], vs1 = lnvs[h * 64 + 2 * lane + 1];
    const float vb0 = lnvb[h * 64 + 2 * lane], vb1 = lnvb[h * 64 + 2 * lane + 1];

    float acc[4][4];
#pragma unroll
    for (int i = 0; i < 4; i++)
#pragma unroll
        for (int j = 0; j < 4; j++) acc[i][j] = 0.f;

    for (int t = 0; t < 4; t++) {
        // Phase A: layernorm 64 rows into smem (8 rows per warp)
#pragma unroll 1
        for (int rr = 0; rr < 8; rr++) {
            int r = warp * 8 + rr;
            int gr = t * 64 + r;
            {
                float2 kv = *(const float2*)(Kslab + (size_t)gr * 64 + 2 * lane);
                float s = kv.x + kv.y;
                float ss = kv.x * kv.x + kv.y * kv.y;
#pragma unroll
                for (int o = 16; o; o >>= 1) {
                    s  += __shfl_xor_sync(0xffffffffu, s, o);
                    ss += __shfl_xor_sync(0xffffffffu, ss, o);
                }
                float mean = s * (1.f / 64.f);
                float var = ss * (1.f / 64.f) - mean * mean;
                float rstd = rsqrtf(var + 1e-6f);
                Ks[r][2 * lane]     = (kv.x - mean) * rstd * ks0 + kb0;
                Ks[r][2 * lane + 1] = (kv.y - mean) * rstd * ks1 + kb1;
            }
            {
                float2 vv = *(const float2*)(Vslab + (size_t)gr * 64 + 2 * lane);
                float s = vv.x + vv.y;
                float ss = vv.x * vv.x + vv.y * vv.y;
#pragma unroll
                for (int o = 16; o; o >>= 1) {
                    s  += __shfl_xor_sync(0xffffffffu, s, o);
                    ss += __shfl_xor_sync(0xffffffffu, ss, o);
                }
                float mean = s * (1.f / 64.f);
                float var = ss * (1.f / 64.f) - mean * mean;
                float rstd = rsqrtf(var + 1e-6f);
                Vs[r][2 * lane]     = (vv.x - mean) * rstd * vs0 + vb0;
                Vs[r][2 * lane + 1] = (vv.y - mean) * rstd * vs1 + vb1;
            }
        }
        __syncthreads();
        // Phase B: P[d][e] += sum_r Ks[r][d] * Vs[r][e]
#pragma unroll 4
        for (int r = 0; r < 64; r++) {
            float4 a = *(const float4*)&Ks[r][ty * 4];
            float4 b = *(const float4*)&Vs[r][tx * 4];
            float av[4] = {a.x, a.y, a.z, a.w};
            float bv[4] = {b.x, b.y, b.z, b.w};
#pragma unroll
            for (int i = 0; i < 4; i++)
#pragma unroll
                for (int j = 0; j < 4; j++) acc[i][j] += av[i] * bv[j];
        }
        __syncthreads();
    }

    float* pp = g_Ppart + ((size_t)bh * NCHUNK + chunk) * 4096;
#pragma unroll
    for (int i = 0; i < 4; i++)
#pragma unroll
        for (int j = 0; j < 4; j++)
            pp[(ty * 4 + i) * 64 + tx * 4 + j] = acc[i][j];
}

// ------------- deterministic reduction of P partials -> d_out p_attn -------
__global__ __launch_bounds__(256) void preduce_kernel(float* __restrict__ out) {
    const int bh = blockIdx.x;
    const float* pp = g_Ppart + (size_t)bh * NCHUNK * 4096;
    float* po = out + ATT_SIZE + (size_t)bh * 4096;
    for (int idx = threadIdx.x; idx < 4096; idx += 256) {
        float s = 0.f;
#pragma unroll
        for (int c = 0; c < NCHUNK; c++) s += pp[(size_t)c * 4096 + idx];
        po[idx] = s * (1.f / (float)NSLAB);
    }
}

// ------------- x = Q_slab (8192x64) @ P (64x64), write att_output ----------
// grid: (128, NBH): 64 rows per block. Reads P from d_out (already final).
__global__ __launch_bounds__(256) void qp_kernel(float* __restrict__ out) {
    __shared__ float Ps[4096];       // [d*64 + e]
    __shared__ float Qs[64 * 68];    // padded rows

    const int bh = blockIdx.y;
    const int rc = blockIdx.x;

    const float* pin = out + ATT_SIZE + (size_t)bh * 4096;
    for (int i = threadIdx.x; i < 1024; i += 256)
        ((float4*)Ps)[i] = ((const float4*)pin)[i];

    const float* qsl = g_Qp + (size_t)bh * (NSLAB * 64) + (size_t)rc * 64 * 64;
    for (int i = threadIdx.x; i < 1024; i += 256) {
        float4 v = ((const float4*)qsl)[i];
        int l = i * 4;
        int row = l >> 6;
        int col = l & 63;
        *(float4*)&Qs[row * 68 + col] = v;
    }
    __syncthreads();

    const int row = threadIdx.x >> 2;          // 0..63
    const int c0 = (threadIdx.x & 3) * 16;     // 0,16,32,48

    float accv[16];
#pragma unroll
    for (int j = 0; j < 16; j++) accv[j] = 0.f;

#pragma unroll 8
    for (int d = 0; d < 64; d++) {
        float qv = Qs[row * 68 + d];
        float4 p0 = *(const float4*)&Ps[d * 64 + c0];
        float4 p1 = *(const float4*)&Ps[d * 64 + c0 + 4];
        float4 p2 = *(const float4*)&Ps[d * 64 + c0 + 8];
        float4 p3 = *(const float4*)&Ps[d * 64 + c0 + 12];
        accv[0] += qv * p0.x;  accv[1] += qv * p0.y;
        accv[2] += qv * p0.z;  accv[3] += qv * p0.w;
        accv[4] += qv * p1.x;  accv[5] += qv * p1.y;
        accv[6] += qv * p1.z;  accv[7] += qv * p1.w;
        accv[8] += qv * p2.x;  accv[9] += qv * p2.y;
        accv[10] += qv * p2.z; accv[11] += qv * p2.w;
        accv[12] += qv * p3.x; accv[13] += qv * p3.y;
        accv[14] += qv * p3.z; accv[15] += qv * p3.w;
    }

    float* orow = out + (size_t)bh * (NSLAB * 64) + (size_t)rc * 64 * 64 + row * 64 + c0;
    *(float4*)(orow + 0)  = make_float4(accv[0], accv[1], accv[2], accv[3]);
    *(float4*)(orow + 4)  = make_float4(accv[4], accv[5], accv[6], accv[7]);
    *(float4*)(orow + 8)  = make_float4(accv[8], accv[9], accv[10], accv[11]);
    *(float4*)(orow + 12) = make_float4(accv[12], accv[13], accv[14], accv[15]);
}

extern "C" void kernel_launch(void* const* d_in, const int* in_sizes, int n_in,
                              void* d_out, int out_size) {
    const float* query = (const float*)d_in[0];
    const float* key   = (const float*)d_in[1];
    const float* value = (const float*)d_in[2];
    const float* Wq    = (const float*)d_in[3];
    const float* Wk    = (const float*)d_in[4];
    const float* Wv    = (const float*)d_in[5];
    const float* lnks  = (const float*)d_in[6];
    const float* lnkb  = (const float*)d_in[7];
    const float* lnvs  = (const float*)d_in[8];
    const float* lnvb  = (const float*)d_in[9];
    float* out = (float*)d_out;

    dim3 gg(GN / 128, GM / 128);   // (8, 256)
    gemm_f32<<<gg, 256>>>(query, Wq, 0);
    gemm_f32<<<gg, 256>>>(key,   Wk, 1);
    gemm_f32<<<gg, 256>>>(value, Wv, 2);

    ln_pkv_kernel<<<dim3(NCHUNK, NBH), 256>>>(lnks, lnkb, lnvs, lnvb);
    preduce_kernel<<<NBH, 256>>>(out);
    qp_kernel<<<dim3(NSLAB / 64, NBH), 256>>>(out);
}

// round 5
// speedup vs baseline: 1.8819x; 1.8819x over previous
#include <cuda_runtime.h>
#include <cuda_bf16.h>
#include <cstdint>

// Problem constants
constexpr int GM = 32768;          // B*S rows
constexpr int GK = 1024;           // F
constexpr int GN = 1024;           // F
constexpr int ATT_SIZE = 33554432; // B*S*F
constexpr int NBH = 64;            // B*H
constexpr int NSLAB = 8192;        // rows per head slab
constexpr int NCHUNK = 32;         // row chunks per slab for P accumulation

// -------------------- scratch (device globals; no allocs allowed) ----------
__device__ float g_Qp[(size_t)GM * GN];
__device__ float g_Kp[(size_t)GM * GN];
__device__ float g_Vp[(size_t)GM * GN];
__device__ float g_Ppart[(size_t)NBH * NCHUNK * 4096];
__device__ __nv_bfloat16 g_ah[3][(size_t)GM * GK];   // activation hi
__device__ __nv_bfloat16 g_al[3][(size_t)GM * GK];   // activation lo
__device__ __nv_bfloat16 g_wth[3][(size_t)GK * GN];  // W^T hi  [N][K]
__device__ __nv_bfloat16 g_wtl[3][(size_t)GK * GN];  // W^T lo  [N][K]

// -------------------- PTX helpers (all baseline sm_80/90 ISA) --------------
__device__ __forceinline__ uint32_t smem_u32(const void* p) {
    uint32_t a;
    asm("{ .reg .u64 t; cvta.to.shared.u64 t, %1; cvt.u32.u64 %0, t; }"
        : "=r"(a) : "l"(p));
    return a;
}
__device__ __forceinline__ void cp16(uint32_t dst, const void* src) {
    asm volatile("cp.async.cg.shared.global [%0], [%1], 16;"
                 :: "r"(dst), "l"(src) : "memory");
}
__device__ __forceinline__ void cp_commit() {
    asm volatile("cp.async.commit_group;" ::: "memory");
}
__device__ __forceinline__ void ldx4(uint32_t* r, uint32_t addr) {
    asm volatile("ldmatrix.sync.aligned.m8n8.x4.shared.b16 {%0,%1,%2,%3}, [%4];"
                 : "=r"(r[0]), "=r"(r[1]), "=r"(r[2]), "=r"(r[3]) : "r"(addr));
}
__device__ __forceinline__ void mma16816(float* c, const uint32_t* a,
                                         const uint32_t* b) {
    asm volatile(
        "mma.sync.aligned.m16n8k16.row.col.f32.bf16.bf16.f32 "
        "{%0,%1,%2,%3}, {%4,%5,%6,%7}, {%8,%9}, {%0,%1,%2,%3};"
        : "+f"(c[0]), "+f"(c[1]), "+f"(c[2]), "+f"(c[3])
        : "r"(a[0]), "r"(a[1]), "r"(a[2]), "r"(a[3]), "r"(b[0]), "r"(b[1]));
}

// -------------------- split/convert kernels --------------------------------
__global__ __launch_bounds__(256) void convert_act(const float* __restrict__ q,
                                                   const float* __restrict__ k,
                                                   const float* __restrict__ v) {
    const int z = blockIdx.y;
    const float4* src = (const float4*)(z == 0 ? q : z == 1 ? k : v);
    __nv_bfloat162* hi = (__nv_bfloat162*)g_ah[z];
    __nv_bfloat162* lo = (__nv_bfloat162*)g_al[z];
    const int N4 = GM * GK / 4;
    for (int i = blockIdx.x * 256 + threadIdx.x; i < N4; i += gridDim.x * 256) {
        float4 x = src[i];
        __nv_bfloat16 h0 = __float2bfloat16(x.x);
        __nv_bfloat16 h1 = __float2bfloat16(x.y);
        __nv_bfloat16 h2 = __float2bfloat16(x.z);
        __nv_bfloat16 h3 = __float2bfloat16(x.w);
        hi[2 * i]     = __halves2bfloat162(h0, h1);
        hi[2 * i + 1] = __halves2bfloat162(h2, h3);
        lo[2 * i] = __halves2bfloat162(
            __float2bfloat16(x.x - __bfloat162float(h0)),
            __float2bfloat16(x.y - __bfloat162float(h1)));
        lo[2 * i + 1] = __halves2bfloat162(
            __float2bfloat16(x.z - __bfloat162float(h2)),
            __float2bfloat16(x.w - __bfloat162float(h3)));
    }
}

__global__ __launch_bounds__(256) void convert_wT(const float* __restrict__ Wq,
                                                  const float* __restrict__ Wk,
                                                  const float* __restrict__ Wv) {
    const int z = blockIdx.z;
    const float* W = (z == 0 ? Wq : z == 1 ? Wk : Wv);
    __shared__ float t[32][33];
    const int tx = threadIdx.x & 31, ty = threadIdx.x >> 5;
    const int n0 = blockIdx.x * 32, k0 = blockIdx.y * 32;
#pragma unroll
    for (int j = 0; j < 32; j += 8)
        t[ty + j][tx] = W[(size_t)(k0 + ty + j) * GN + n0 + tx];
    __syncthreads();
#pragma unroll
    for (int j = 0; j < 32; j += 8) {
        float x = t[tx][ty + j];
        __nv_bfloat16 h = __float2bfloat16(x);
        float l = x - __bfloat162float(h);
        size_t o = (size_t)(n0 + ty + j) * GK + k0 + tx;
        g_wth[z][o] = h;
        g_wtl[z][o] = __float2bfloat16(l);
    }
}

// -------------------- HMMA (mma.sync) GEMM ---------------------------------
// C(32768x1024) = A * W; fused 3-pass bf16 split: Ah*Bh + Ah*Bl + Al*Bh.
// CTA tile 128x128, BK=64, 8 warps (2Mx4N -> warp tile 64x32),
// 3-stage cp.async pipeline; SW128 xor swizzle on 128B smem rows.
constexpr int SUBT = 16384;              // one 128x64 bf16 subtile
constexpr int STG = 4 * SUBT;            // Ah | Al | Bh | Bl = 64KB
constexpr int NST = 3;
constexpr int GEMM_SMEM = NST * STG;     // 192KB

__global__ __launch_bounds__(256, 1) void gemm_mma() {
    extern __shared__ char smem[];
    const uint32_t sb = smem_u32(smem);
    const int tid = threadIdx.x;
    const int wid = tid >> 5;
    const int lane = tid & 31;
    const int z = blockIdx.z;

    const __nv_bfloat16* Ah = g_ah[z];
    const __nv_bfloat16* Al = g_al[z];
    const __nv_bfloat16* Bh = g_wth[z];
    const __nv_bfloat16* Bl = g_wtl[z];
    float* C = (z == 0) ? g_Qp : (z == 1) ? g_Kp : g_Vp;
    const size_t rowBase = (size_t)blockIdx.y * 128;
    const size_t colBase = (size_t)blockIdx.x * 128;

    // ---- async stage loader: 4 subtiles x 1024 16B-segments ----
    auto load_stage = [&](int chunk, int st) {
        const int k0 = chunk * 64;
        const uint32_t base = sb + st * STG;
#pragma unroll
        for (int s = 0; s < 4; s++) {
            const __nv_bfloat16* P = (s == 0) ? Ah : (s == 1) ? Al
                                   : (s == 2) ? Bh : Bl;
            const size_t rb = (s < 2) ? rowBase : colBase;
            const uint32_t sbb = base + s * SUBT;
#pragma unroll
            for (int j = 0; j < 4; j++) {
                int idx = tid + 256 * j;
                int r = idx >> 3, c = idx & 7;
                cp16(sbb + r * 128 + ((c ^ (r & 7)) * 16),
                     P + (rb + r) * GK + k0 + c * 8);
            }
        }
        cp_commit();
    };

    load_stage(0, 0);
    load_stage(1, 1);

    const int wm = wid >> 2;        // 0..1  (M)
    const int wn = wid & 3;         // 0..3  (N)
    const int g = lane >> 3;        // ldmatrix group
    const int lr = lane & 7;
    const int aRow = (g & 1) * 8 + lr;       // A: matrix row within 16
    const int aC = g >> 1;                   // A: k-chunk select
    const int bRow = (g >> 1) * 8 + lr;      // B: n row within 16
    const int bC = g & 1;                    // B: k-chunk select

    float acc[4][4][4];
#pragma unroll
    for (int i = 0; i < 4; i++)
#pragma unroll
        for (int j = 0; j < 4; j++)
#pragma unroll
            for (int q = 0; q < 4; q++) acc[i][j][q] = 0.f;

#pragma unroll 1
    for (int c = 0; c < 16; c++) {
        asm volatile("cp.async.wait_group 1;" ::: "memory");
        __syncthreads();
        if (c + 2 < 16) load_stage(c + 2, (c + 2) % 3);

        const uint32_t stB = sb + (c % 3) * STG;
        const uint32_t AhB = stB, AlB = stB + SUBT;
        const uint32_t BhB = stB + 2 * SUBT, BlB = stB + 3 * SUBT;

#pragma unroll
        for (int ks = 0; ks < 4; ks++) {
            uint32_t ah[4][4], al[4][4];
#pragma unroll
            for (int mt = 0; mt < 4; mt++) {
                int row = wm * 64 + mt * 16 + aRow;
                uint32_t col = (uint32_t)(((ks * 2 + aC) ^ lr) * 16);
                ldx4(ah[mt], AhB + row * 128 + col);
                ldx4(al[mt], AlB + row * 128 + col);
            }
            uint32_t bh[2][4], bl[2][4];
#pragma unroll
            for (int pr = 0; pr < 2; pr++) {
                int row = wn * 32 + pr * 16 + bRow;
                uint32_t col = (uint32_t)(((ks * 2 + bC) ^ lr) * 16);
                ldx4(bh[pr], BhB + row * 128 + col);
                ldx4(bl[pr], BlB + row * 128 + col);
            }
#pragma unroll
            for (int mt = 0; mt < 4; mt++)
#pragma unroll
                for (int nt = 0; nt < 4; nt++) {
                    const uint32_t* bH = &bh[nt >> 1][(nt & 1) * 2];
                    const uint32_t* bL = &bl[nt >> 1][(nt & 1) * 2];
                    mma16816(acc[mt][nt], ah[mt], bH);
                    mma16816(acc[mt][nt], ah[mt], bL);
                    mma16816(acc[mt][nt], al[mt], bH);
                }
        }
    }

    // ---- epilogue: direct global stores (float2 per row-fragment) ----
    const int tg = lane >> 2, tt = lane & 3;
#pragma unroll
    for (int mt = 0; mt < 4; mt++) {
#pragma unroll
        for (int nt = 0; nt < 4; nt++) {
            size_t row0 = rowBase + wm * 64 + mt * 16 + tg;
            size_t col = colBase + wn * 32 + nt * 8 + 2 * tt;
            *(float2*)(C + row0 * GN + col) =
                make_float2(acc[mt][nt][0], acc[mt][nt][1]);
            *(float2*)(C + (row0 + 8) * GN + col) =
                make_float2(acc[mt][nt][2], acc[mt][nt][3]);
        }
    }
}

// ------------- LayerNorm(K), LayerNorm(V), partial P = Kn^T Vn -------------
__global__ __launch_bounds__(256) void ln_pkv_kernel(const float* __restrict__ lnks,
                                                     const float* __restrict__ lnkb,
                                                     const float* __restrict__ lnvs,
                                                     const float* __restrict__ lnvb) {
    __shared__ float Ks[64][64];
    __shared__ float Vs[64][64];

    const int bh = blockIdx.y;
    const int chunk = blockIdx.x;
    const int h = bh & 15;

    const float* Kslab = g_Kp + (size_t)bh * (NSLAB * 64) + (size_t)chunk * 256 * 64;
    const float* Vslab = g_Vp + (size_t)bh * (NSLAB * 64) + (size_t)chunk * 256 * 64;

    const int tid = threadIdx.x;
    const int lane = tid & 31;
    const int warp = tid >> 5;
    const int tx = tid & 15;
    const int ty = tid >> 4;

    const float ks0 = lnks[h * 64 + 2 * lane], ks1 = lnks[h * 64 + 2 * lane + 1];
    const float kb0 = lnkb[h * 64 + 2 * lane], kb1 = lnkb[h * 64 + 2 * lane + 1];
    const float vs0 = lnvs[h * 64 + 2 * lane], vs1 = lnvs[h * 64 + 2 * lane + 1];
    const float vb0 = lnvb[h * 64 + 2 * lane], vb1 = lnvb[h * 64 + 2 * lane + 1];

    float acc[4][4];
#pragma unroll
    for (int i = 0; i < 4; i++)
#pragma unroll
        for (int j = 0; j < 4; j++) acc[i][j] = 0.f;

    for (int t = 0; t < 4; t++) {
#pragma unroll 1
        for (int rr = 0; rr < 8; rr++) {
            int r = warp * 8 + rr;
            int gr = t * 64 + r;
            {
                float2 kv = *(const float2*)(Kslab + (size_t)gr * 64 + 2 * lane);
                float s = kv.x + kv.y;
                float ss = kv.x * kv.x + kv.y * kv.y;
#pragma unroll
                for (int o = 16; o; o >>= 1) {
                    s  += __shfl_xor_sync(0xffffffffu, s, o);
                    ss += __shfl_xor_sync(0xffffffffu, ss, o);
                }
                float mean = s * (1.f / 64.f);
                float var = ss * (1.f / 64.f) - mean * mean;
                float rstd = rsqrtf(var + 1e-6f);
                Ks[r][2 * lane]     = (kv.x - mean) * rstd * ks0 + kb0;
                Ks[r][2 * lane + 1] = (kv.y - mean) * rstd * ks1 + kb1;
            }
            {
                float2 vv = *(const float2*)(Vslab + (size_t)gr * 64 + 2 * lane);
                float s = vv.x + vv.y;
                float ss = vv.x * vv.x + vv.y * vv.y;
#pragma unroll
                for (int o = 16; o; o >>= 1) {
                    s  += __shfl_xor_sync(0xffffffffu, s, o);
                    ss += __shfl_xor_sync(0xffffffffu, ss, o);
                }
                float mean = s * (1.f / 64.f);
                float var = ss * (1.f / 64.f) - mean * mean;
                float rstd = rsqrtf(var + 1e-6f);
                Vs[r][2 * lane]     = (vv.x - mean) * rstd * vs0 + vb0;
                Vs[r][2 * lane + 1] = (vv.y - mean) * rstd * vs1 + vb1;
            }
        }
        __syncthreads();
#pragma unroll 4
        for (int r = 0; r < 64; r++) {
            float4 a = *(const float4*)&Ks[r][ty * 4];
            float4 b = *(const float4*)&Vs[r][tx * 4];
            float av[4] = {a.x, a.y, a.z, a.w};
            float bv[4] = {b.x, b.y, b.z, b.w};
#pragma unroll
            for (int i = 0; i < 4; i++)
#pragma unroll
                for (int j = 0; j < 4; j++) acc[i][j] += av[i] * bv[j];
        }
        __syncthreads();
    }

    float* pp = g_Ppart + ((size_t)bh * NCHUNK + chunk) * 4096;
#pragma unroll
    for (int i = 0; i < 4; i++)
#pragma unroll
        for (int j = 0; j < 4; j++)
            pp[(ty * 4 + i) * 64 + tx * 4 + j] = acc[i][j];
}

// ------------- deterministic reduction of P partials -> d_out p_attn -------
__global__ __launch_bounds__(256) void preduce_kernel(float* __restrict__ out) {
    const int bh = blockIdx.x;
    const float* pp = g_Ppart + (size_t)bh * NCHUNK * 4096;
    float* po = out + ATT_SIZE + (size_t)bh * 4096;
    for (int idx = threadIdx.x; idx < 4096; idx += 256) {
        float s = 0.f;
#pragma unroll
        for (int c = 0; c < NCHUNK; c++) s += pp[(size_t)c * 4096 + idx];
        po[idx] = s * (1.f / (float)NSLAB);
    }
}

// ------------- x = Q_slab (8192x64) @ P (64x64), write att_output ----------
__global__ __launch_bounds__(256) void qp_kernel(float* __restrict__ out) {
    __shared__ float Ps[4096];
    __shared__ float Qs[64 * 68];

    const int bh = blockIdx.y;
    const int rc = blockIdx.x;

    const float* pin = out + ATT_SIZE + (size_t)bh * 4096;
    for (int i = threadIdx.x; i < 1024; i += 256)
        ((float4*)Ps)[i] = ((const float4*)pin)[i];

    const float* qsl = g_Qp + (size_t)bh * (NSLAB * 64) + (size_t)rc * 64 * 64;
    for (int i = threadIdx.x; i < 1024; i += 256) {
        float4 v = ((const float4*)qsl)[i];
        int l = i * 4;
        int row = l >> 6;
        int col = l & 63;
        *(float4*)&Qs[row * 68 + col] = v;
    }
    __syncthreads();

    const int row = threadIdx.x >> 2;
    const int c0 = (threadIdx.x & 3) * 16;

    float accv[16];
#pragma unroll
    for (int j = 0; j < 16; j++) accv[j] = 0.f;

#pragma unroll 8
    for (int d = 0; d < 64; d++) {
        float qv = Qs[row * 68 + d];
        float4 p0 = *(const float4*)&Ps[d * 64 + c0];
        float4 p1 = *(const float4*)&Ps[d * 64 + c0 + 4];
        float4 p2 = *(const float4*)&Ps[d * 64 + c0 + 8];
        float4 p3 = *(const float4*)&Ps[d * 64 + c0 + 12];
        accv[0] += qv * p0.x;  accv[1] += qv * p0.y;
        accv[2] += qv * p0.z;  accv[3] += qv * p0.w;
        accv[4] += qv * p1.x;  accv[5] += qv * p1.y;
        accv[6] += qv * p1.z;  accv[7] += qv * p1.w;
        accv[8] += qv * p2.x;  accv[9] += qv * p2.y;
        accv[10] += qv * p2.z; accv[11] += qv * p2.w;
        accv[12] += qv * p3.x; accv[13] += qv * p3.y;
        accv[14] += qv * p3.z; accv[15] += qv * p3.w;
    }

    float* orow = out + (size_t)bh * (NSLAB * 64) + (size_t)rc * 64 * 64 + row * 64 + c0;
    *(float4*)(orow + 0)  = make_float4(accv[0], accv[1], accv[2], accv[3]);
    *(float4*)(orow + 4)  = make_float4(accv[4], accv[5], accv[6], accv[7]);
    *(float4*)(orow + 8)  = make_float4(accv[8], accv[9], accv[10], accv[11]);
    *(float4*)(orow + 12) = make_float4(accv[12], accv[13], accv[14], accv[15]);
}

extern "C" void kernel_launch(void* const* d_in, const int* in_sizes, int n_in,
                              void* d_out, int out_size) {
    const float* query = (const float*)d_in[0];
    const float* key   = (const float*)d_in[1];
    const float* value = (const float*)d_in[2];
    const float* Wq    = (const float*)d_in[3];
    const float* Wk    = (const float*)d_in[4];
    const float* Wv    = (const float*)d_in[5];
    const float* lnks  = (const float*)d_in[6];
    const float* lnkb  = (const float*)d_in[7];
    const float* lnvs  = (const float*)d_in[8];
    const float* lnvb  = (const float*)d_in[9];
    float* out = (float*)d_out;

    cudaFuncSetAttribute(gemm_mma, cudaFuncAttributeMaxDynamicSharedMemorySize,
                         GEMM_SMEM);

    convert_act<<<dim3(4096, 3), 256>>>(query, key, value);
    convert_wT<<<dim3(32, 32, 3), 256>>>(Wq, Wk, Wv);

    gemm_mma<<<dim3(GN / 128, GM / 128, 3), 256, GEMM_SMEM>>>();

    ln_pkv_kernel<<<dim3(NCHUNK, NBH), 256>>>(lnks, lnkb, lnvs, lnvb);
    preduce_kernel<<<NBH, 256>>>(out);
    qp_kernel<<<dim3(NSLAB / 64, NBH), 256>>>(out);
}

// round 8
// speedup vs baseline: 2.2225x; 1.1810x over previous
#include <cuda_runtime.h>
#include <cuda_bf16.h>
#include <cstdint>

// Problem constants
constexpr int GM = 32768;          // B*S rows
constexpr int GK = 1024;           // F
constexpr int GN = 1024;           // F
constexpr int ATT_SIZE = 33554432; // B*S*F
constexpr int NBH = 64;            // B*H
constexpr int NSLAB = 8192;        // rows per head slab
constexpr int NCHUNK = 32;         // row chunks per slab for P accumulation

// -------------------- scratch (device globals; no allocs allowed) ----------
__device__ float g_Qp[(size_t)GM * GN];
__device__ float g_Kp[(size_t)GM * GN];
__device__ float g_Vp[(size_t)GM * GN];
__device__ float g_Ppart[(size_t)NBH * NCHUNK * 4096];
__device__ float g_wt[3][(size_t)GK * GN];   // W^T, tf32-rounded, [N][K]

// -------------------- PTX helpers (baseline sm_80 ISA) ---------------------
__device__ __forceinline__ uint32_t smem_u32(const void* p) {
    uint32_t a;
    asm("{ .reg .u64 t; cvta.to.shared.u64 t, %1; cvt.u32.u64 %0, t; }"
        : "=r"(a) : "l"(p));
    return a;
}
__device__ __forceinline__ void cp16(uint32_t dst, const void* src) {
    asm volatile("cp.async.cg.shared.global [%0], [%1], 16;"
                 :: "r"(dst), "l"(src) : "memory");
}
__device__ __forceinline__ void cp_commit() {
    asm volatile("cp.async.commit_group;" ::: "memory");
}
__device__ __forceinline__ void ldx4(uint32_t* r, uint32_t addr) {
    asm volatile("ldmatrix.sync.aligned.m8n8.x4.shared.b16 {%0,%1,%2,%3}, [%4];"
                 : "=r"(r[0]), "=r"(r[1]), "=r"(r[2]), "=r"(r[3]) : "r"(addr));
}
__device__ __forceinline__ uint32_t tf32r(uint32_t x) {
    uint32_t r;
    asm("cvt.rna.tf32.f32 %0, %1;" : "=r"(r) : "f"(__uint_as_float(x)));
    return r;
}
__device__ __forceinline__ void mma_tf32(float* c, const uint32_t* a,
                                         const uint32_t* b) {
    asm volatile(
        "mma.sync.aligned.m16n8k8.row.col.f32.tf32.tf32.f32 "
        "{%0,%1,%2,%3}, {%4,%5,%6,%7}, {%8,%9}, {%0,%1,%2,%3};"
        : "+f"(c[0]), "+f"(c[1]), "+f"(c[2]), "+f"(c[3])
        : "r"(a[0]), "r"(a[1]), "r"(a[2]), "r"(a[3]), "r"(b[0]), "r"(b[1]));
}

// -------------------- W transpose + tf32 round -----------------------------
__global__ __launch_bounds__(256) void convert_wT(const float* __restrict__ Wq,
                                                  const float* __restrict__ Wk,
                                                  const float* __restrict__ Wv) {
    const int z = blockIdx.z;
    const float* W = (z == 0 ? Wq : z == 1 ? Wk : Wv);
    __shared__ float t[32][33];
    const int tx = threadIdx.x & 31, ty = threadIdx.x >> 5;
    const int n0 = blockIdx.x * 32, k0 = blockIdx.y * 32;
#pragma unroll
    for (int j = 0; j < 32; j += 8)
        t[ty + j][tx] = W[(size_t)(k0 + ty + j) * GN + n0 + tx];
    __syncthreads();
#pragma unroll
    for (int j = 0; j < 32; j += 8) {
        uint32_t r = tf32r(__float_as_uint(t[tx][ty + j]));
        g_wt[z][(size_t)(n0 + ty + j) * GK + k0 + tx] = __uint_as_float(r);
    }
}

// tiny pad launches so ncu's captured launch index lands on gemm_tf32
__global__ void pad_kernel() {}

// -------------------- tf32 single-pass GEMM --------------------------------
// C(32768x1024) = A * W.  CTA tile 128x128, BK=64 (fp32: 256B rows, swizzled
// per 128B half), 8 warps (2Mx4N; warp tile 64x32), 3-stage cp.async pipeline.
// A raw fp32 from inputs, cvt.rna.tf32 in-register; B pre-rounded in g_wt.
constexpr int STG = 65536;          // A 32KB + B 32KB per stage
constexpr int NST = 3;
constexpr int GEMM_SMEM = NST * STG; // 192KB

__global__ __launch_bounds__(256, 1) void gemm_tf32(const float* __restrict__ q,
                                                    const float* __restrict__ k,
                                                    const float* __restrict__ v) {
    extern __shared__ char smem[];
    const uint32_t sb = smem_u32(smem);
    const int tid = threadIdx.x;
    const int wid = tid >> 5;
    const int lane = tid & 31;
    const int z = blockIdx.z;

    const float* A = (z == 0) ? q : (z == 1) ? k : v;
    const float* B = g_wt[z];
    float* C = (z == 0) ? g_Qp : (z == 1) ? g_Kp : g_Vp;
    const size_t rowBase = (size_t)blockIdx.y * 128;
    const size_t colBase = (size_t)blockIdx.x * 128;

    // stage loader: A 128x64 fp32 + B 128x64 fp32; 16B segs, swizzled halves
    auto load_stage = [&](int chunk, int st) {
        const int k0 = chunk * 64;
        const uint32_t base = sb + st * STG;
#pragma unroll
        for (int j = 0; j < 8; j++) {
            int idx = tid + 256 * j;
            int r = idx >> 4, s = idx & 15;
            cp16(base + r * 256 + ((s >> 3) * 128) + (((s & 7) ^ (r & 7)) * 16),
                 A + (rowBase + r) * GK + k0 + s * 4);
        }
#pragma unroll
        for (int j = 0; j < 8; j++) {
            int idx = tid + 256 * j;
            int r = idx >> 4, s = idx & 15;
            cp16(base + 32768 + r * 256 + ((s >> 3) * 128) +
                     (((s & 7) ^ (r & 7)) * 16),
                 B + (colBase + r) * GK + k0 + s * 4);
        }
        cp_commit();
    };

    load_stage(0, 0);
    load_stage(1, 1);

    const int wm = wid >> 2;        // 0..1  (M)
    const int wn = wid & 3;         // 0..3  (N)
    const int g = lane >> 3;        // ldmatrix group
    const int lr = lane & 7;
    const int aRow = (g & 1) * 8 + lr;   // A row within 16
    const int aC = g >> 1;               // A seg select
    const int bRow = (g >> 1) * 8 + lr;  // B n-row within 16
    const int bC = g & 1;                // B seg select

    float acc[4][4][4];
#pragma unroll
    for (int i = 0; i < 4; i++)
#pragma unroll
        for (int j = 0; j < 4; j++)
#pragma unroll
            for (int p = 0; p < 4; p++) acc[i][j][p] = 0.f;

#pragma unroll 1
    for (int c = 0; c < 16; c++) {
        asm volatile("cp.async.wait_group 1;" ::: "memory");
        __syncthreads();
        if (c + 2 < 16) load_stage(c + 2, (c + 2) % 3);

        const uint32_t AB = sb + (c % 3) * STG;
        const uint32_t BB = AB + 32768;

#pragma unroll
        for (int ks = 0; ks < 8; ks++) {
            uint32_t af[4][4];
#pragma unroll
            for (int mt = 0; mt < 4; mt++) {
                int row = wm * 64 + mt * 16 + aRow;
                int seg = 2 * ks + aC;
                ldx4(af[mt], AB + row * 256 + ((seg >> 3) * 128) +
                                 (((seg & 7) ^ lr) * 16));
#pragma unroll
                for (int p = 0; p < 4; p++) af[mt][p] = tf32r(af[mt][p]);
            }
            uint32_t bf[2][4];
#pragma unroll
            for (int pr = 0; pr < 2; pr++) {
                int row = wn * 32 + pr * 16 + bRow;
                int seg = 2 * ks + bC;
                ldx4(bf[pr], BB + row * 256 + ((seg >> 3) * 128) +
                                 (((seg & 7) ^ lr) * 16));
            }
#pragma unroll
            for (int mt = 0; mt < 4; mt++)
#pragma unroll
                for (int nt = 0; nt < 4; nt++)
                    mma_tf32(acc[mt][nt], af[mt], &bf[nt >> 1][(nt & 1) * 2]);
        }
    }

    // epilogue: direct global stores
    const int tg = lane >> 2, tt = lane & 3;
#pragma unroll
    for (int mt = 0; mt < 4; mt++) {
#pragma unroll
        for (int nt = 0; nt < 4; nt++) {
            size_t row0 = rowBase + wm * 64 + mt * 16 + tg;
            size_t col = colBase + wn * 32 + nt * 8 + 2 * tt;
            *(float2*)(C + row0 * GN + col) =
                make_float2(acc[mt][nt][0], acc[mt][nt][1]);
            *(float2*)(C + (row0 + 8) * GN + col) =
                make_float2(acc[mt][nt][2], acc[mt][nt][3]);
        }
    }
}

// ------------- LayerNorm(K), LayerNorm(V), partial P = Kn^T Vn -------------
__global__ __launch_bounds__(256) void ln_pkv_kernel(const float* __restrict__ lnks,
                                                     const float* __restrict__ lnkb,
                                                     const float* __restrict__ lnvs,
                                                     const float* __restrict__ lnvb) {
    __shared__ float Ks[64][64];
    __shared__ float Vs[64][64];

    const int bh = blockIdx.y;
    const int chunk = blockIdx.x;
    const int h = bh & 15;

    const float* Kslab = g_Kp + (size_t)bh * (NSLAB * 64) + (size_t)chunk * 256 * 64;
    const float* Vslab = g_Vp + (size_t)bh * (NSLAB * 64) + (size_t)chunk * 256 * 64;

    const int tid = threadIdx.x;
    const int lane = tid & 31;
    const int warp = tid >> 5;
    const int tx = tid & 15;
    const int ty = tid >> 4;

    const float ks0 = lnks[h * 64 + 2 * lane], ks1 = lnks[h * 64 + 2 * lane + 1];
    const float kb0 = lnkb[h * 64 + 2 * lane], kb1 = lnkb[h * 64 + 2 * lane + 1];
    const float vs0 = lnvs[h * 64 + 2 * lane], vs1 = lnvs[h * 64 + 2 * lane + 1];
    const float vb0 = lnvb[h * 64 + 2 * lane], vb1 = lnvb[h * 64 + 2 * lane + 1];

    float acc[4][4];
#pragma unroll
    for (int i = 0; i < 4; i++)
#pragma unroll
        for (int j = 0; j < 4; j++) acc[i][j] = 0.f;

    for (int t = 0; t < 4; t++) {
#pragma unroll 1
        for (int rr = 0; rr < 8; rr++) {
            int r = warp * 8 + rr;
            int gr = t * 64 + r;
            {
                float2 kv = *(const float2*)(Kslab + (size_t)gr * 64 + 2 * lane);
                float s = kv.x + kv.y;
                float ss = kv.x * kv.x + kv.y * kv.y;
#pragma unroll
                for (int o = 16; o; o >>= 1) {
                    s  += __shfl_xor_sync(0xffffffffu, s, o);
                    ss += __shfl_xor_sync(0xffffffffu, ss, o);
                }
                float mean = s * (1.f / 64.f);
                float var = ss * (1.f / 64.f) - mean * mean;
                float rstd = rsqrtf(var + 1e-6f);
                Ks[r][2 * lane]     = (kv.x - mean) * rstd * ks0 + kb0;
                Ks[r][2 * lane + 1] = (kv.y - mean) * rstd * ks1 + kb1;
            }
            {
                float2 vv = *(const float2*)(Vslab + (size_t)gr * 64 + 2 * lane);
                float s = vv.x + vv.y;
                float ss = vv.x * vv.x + vv.y * vv.y;
#pragma unroll
                for (int o = 16; o; o >>= 1) {
                    s  += __shfl_xor_sync(0xffffffffu, s, o);
                    ss += __shfl_xor_sync(0xffffffffu, ss, o);
                }
                float mean = s * (1.f / 64.f);
                float var = ss * (1.f / 64.f) - mean * mean;
                float rstd = rsqrtf(var + 1e-6f);
                Vs[r][2 * lane]     = (vv.x - mean) * rstd * vs0 + vb0;
                Vs[r][2 * lane + 1] = (vv.y - mean) * rstd * vs1 + vb1;
            }
        }
        __syncthreads();
#pragma unroll 4
        for (int r = 0; r < 64; r++) {
            float4 a = *(const float4*)&Ks[r][ty * 4];
            float4 b = *(const float4*)&Vs[r][tx * 4];
            float av[4] = {a.x, a.y, a.z, a.w};
            float bv[4] = {b.x, b.y, b.z, b.w};
#pragma unroll
            for (int i = 0; i < 4; i++)
#pragma unroll
                for (int j = 0; j < 4; j++) acc[i][j] += av[i] * bv[j];
        }
        __syncthreads();
    }

    float* pp = g_Ppart + ((size_t)bh * NCHUNK + chunk) * 4096;
#pragma unroll
    for (int i = 0; i < 4; i++)
#pragma unroll
        for (int j = 0; j < 4; j++)
            pp[(ty * 4 + i) * 64 + tx * 4 + j] = acc[i][j];
}

// ------------- deterministic reduction of P partials -> d_out p_attn -------
__global__ __launch_bounds__(256) void preduce_kernel(float* __restrict__ out) {
    const int bh = blockIdx.x;
    const float* pp = g_Ppart + (size_t)bh * NCHUNK * 4096;
    float* po = out + ATT_SIZE + (size_t)bh * 4096;
    for (int idx = threadIdx.x; idx < 4096; idx += 256) {
        float s = 0.f;
#pragma unroll
        for (int c = 0; c < NCHUNK; c++) s += pp[(size_t)c * 4096 + idx];
        po[idx] = s * (1.f / (float)NSLAB);
    }
}

// ------------- x = Q_slab (8192x64) @ P (64x64), write att_output ----------
__global__ __launch_bounds__(256) void qp_kernel(float* __restrict__ out) {
    __shared__ float Ps[4096];
    __shared__ float Qs[64 * 68];

    const int bh = blockIdx.y;
    const int rc = blockIdx.x;

    const float* pin = out + ATT_SIZE + (size_t)bh * 4096;
    for (int i = threadIdx.x; i < 1024; i += 256)
        ((float4*)Ps)[i] = ((const float4*)pin)[i];

    const float* qsl = g_Qp + (size_t)bh * (NSLAB * 64) + (size_t)rc * 64 * 64;
    for (int i = threadIdx.x; i < 1024; i += 256) {
        float4 vv = ((const float4*)qsl)[i];
        int l = i * 4;
        int row = l >> 6;
        int col = l & 63;
        *(float4*)&Qs[row * 68 + col] = vv;
    }
    __syncthreads();

    const int row = threadIdx.x >> 2;
    const int c0 = (threadIdx.x & 3) * 16;

    float accv[16];
#pragma unroll
    for (int j = 0; j < 16; j++) accv[j] = 0.f;

#pragma unroll 8
    for (int d = 0; d < 64; d++) {
        float qv = Qs[row * 68 + d];
        float4 p0 = *(const float4*)&Ps[d * 64 + c0];
        float4 p1 = *(const float4*)&Ps[d * 64 + c0 + 4];
        float4 p2 = *(const float4*)&Ps[d * 64 + c0 + 8];
        float4 p3 = *(const float4*)&Ps[d * 64 + c0 + 12];
        accv[0] += qv * p0.x;  accv[1] += qv * p0.y;
        accv[2] += qv * p0.z;  accv[3] += qv * p0.w;
        accv[4] += qv * p1.x;  accv[5] += qv * p1.y;
        accv[6] += qv * p1.z;  accv[7] += qv * p1.w;
        accv[8] += qv * p2.x;  accv[9] += qv * p2.y;
        accv[10] += qv * p2.z; accv[11] += qv * p2.w;
        accv[12] += qv * p3.x; accv[13] += qv * p3.y;
        accv[14] += qv * p3.z; accv[15] += qv * p3.w;
    }

    float* orow = out + (size_t)bh * (NSLAB * 64) + (size_t)rc * 64 * 64 + row * 64 + c0;
    *(float4*)(orow + 0)  = make_float4(accv[0], accv[1], accv[2], accv[3]);
    *(float4*)(orow + 4)  = make_float4(accv[4], accv[5], accv[6], accv[7]);
    *(float4*)(orow + 8)  = make_float4(accv[8], accv[9], accv[10], accv[11]);
    *(float4*)(orow + 12) = make_float4(accv[12], accv[13], accv[14], accv[15]);
}

extern "C" void kernel_launch(void* const* d_in, const int* in_sizes, int n_in,
                              void* d_out, int out_size) {
    const float* query = (const float*)d_in[0];
    const float* key   = (const float*)d_in[1];
    const float* value = (const float*)d_in[2];
    const float* Wq    = (const float*)d_in[3];
    const float* Wk    = (const float*)d_in[4];
    const float* Wv    = (const float*)d_in[5];
    const float* lnks  = (const float*)d_in[6];
    const float* lnkb  = (const float*)d_in[7];
    const float* lnvs  = (const float*)d_in[8];
    const float* lnvb  = (const float*)d_in[9];
    float* out = (float*)d_out;

    cudaFuncSetAttribute(gemm_tf32, cudaFuncAttributeMaxDynamicSharedMemorySize,
                         GEMM_SMEM);

    convert_wT<<<dim3(32, 32, 3), 256>>>(Wq, Wk, Wv);   // launch 1
    pad_kernel<<<1, 32>>>();                            // launch 2
    pad_kernel<<<1, 32>>>();                            // launch 3
    gemm_tf32<<<dim3(GN / 128, GM / 128, 3), 256, GEMM_SMEM>>>(query, key, value); // 4
    ln_pkv_kernel<<<dim3(NCHUNK, NBH), 256>>>(lnks, lnkb, lnvs, lnvb);
    preduce_kernel<<<NBH, 256>>>(out);
    qp_kernel<<<dim3(NSLAB / 64, NBH), 256>>>(out);
}

// round 12
// speedup vs baseline: 2.4361x; 1.0961x over previous
#include <cuda_runtime.h>
#include <cuda_bf16.h>
#include <cstdint>

// Problem constants
constexpr int GM = 32768;          // B*S rows
constexpr int GK = 1024;           // F
constexpr int GN = 1024;           // F
constexpr int ATT_SIZE = 33554432; // B*S*F
constexpr int NBH = 64;            // B*H
constexpr int NSLAB = 8192;        // rows per head slab
constexpr int NCHUNK = 32;         // row chunks per slab for P accumulation

// -------------------- scratch (device globals; no allocs allowed) ----------
__device__ float g_Qp[(size_t)GM * GN];
__device__ float g_Kp[(size_t)GM * GN];
__device__ float g_Vp[(size_t)GM * GN];
__device__ float g_Ppart[(size_t)NBH * NCHUNK * 4096];
__device__ float g_wt[3][(size_t)GK * GN];   // W^T, tf32-rounded, [N][K]

// -------------------- PTX helpers (baseline sm_80 ISA) ---------------------
__device__ __forceinline__ uint32_t smem_u32(const void* p) {
    uint32_t a;
    asm("{ .reg .u64 t; cvta.to.shared.u64 t, %1; cvt.u32.u64 %0, t; }"
        : "=r"(a) : "l"(p));
    return a;
}
__device__ __forceinline__ void cp16(uint32_t dst, const void* src) {
    asm volatile("cp.async.cg.shared.global [%0], [%1], 16;"
                 :: "r"(dst), "l"(src) : "memory");
}
__device__ __forceinline__ void cp_commit() {
    asm volatile("cp.async.commit_group;" ::: "memory");
}
__device__ __forceinline__ void ldx4(uint32_t* r, uint32_t addr) {
    asm volatile("ldmatrix.sync.aligned.m8n8.x4.shared.b16 {%0,%1,%2,%3}, [%4];"
                 : "=r"(r[0]), "=r"(r[1]), "=r"(r[2]), "=r"(r[3]) : "r"(addr));
}
__device__ __forceinline__ uint32_t tf32r(uint32_t x) {
    uint32_t r;
    asm("cvt.rna.tf32.f32 %0, %1;" : "=r"(r) : "f"(__uint_as_float(x)));
    return r;
}
__device__ __forceinline__ void mma_tf32(float* c, const uint32_t* a,
                                         const uint32_t* b) {
    asm volatile(
        "mma.sync.aligned.m16n8k8.row.col.f32.tf32.tf32.f32 "
        "{%0,%1,%2,%3}, {%4,%5,%6,%7}, {%8,%9}, {%0,%1,%2,%3};"
        : "+f"(c[0]), "+f"(c[1]), "+f"(c[2]), "+f"(c[3])
        : "r"(a[0]), "r"(a[1]), "r"(a[2]), "r"(a[3]), "r"(b[0]), "r"(b[1]));
}

// -------------------- W transpose + tf32 round -----------------------------
__global__ __launch_bounds__(256) void convert_wT(const float* __restrict__ Wq,
                                                  const float* __restrict__ Wk,
                                                  const float* __restrict__ Wv) {
    const int z = blockIdx.z;
    const float* W = (z == 0 ? Wq : z == 1 ? Wk : Wv);
    __shared__ float t[32][33];
    const int tx = threadIdx.x & 31, ty = threadIdx.x >> 5;
    const int n0 = blockIdx.x * 32, k0 = blockIdx.y * 32;
#pragma unroll
    for (int j = 0; j < 32; j += 8)
        t[ty + j][tx] = W[(size_t)(k0 + ty + j) * GN + n0 + tx];
    __syncthreads();
#pragma unroll
    for (int j = 0; j < 32; j += 8) {
        uint32_t r = tf32r(__float_as_uint(t[tx][ty + j]));
        g_wt[z][(size_t)(n0 + ty + j) * GK + k0 + tx] = __uint_as_float(r);
    }
}

// tiny pad launches so ncu's captured launch index lands on gemm_tf32
__global__ void pad_kernel() {}

// -------------------- tf32 single-pass GEMM --------------------------------
// C(32768x1024) = A * W.  CTA tile 128x256, BK=64 (fp32: 256B rows, swizzled
// per 128B half), 8 warps (2Mx4N; warp tile 64x64), 2-stage cp.async pipeline.
// A raw fp32 from inputs, cvt.rna.tf32 in-register; B pre-rounded in g_wt.
constexpr int STG = 98304;           // A 32KB + B 64KB per stage
constexpr int NST = 2;
constexpr int GEMM_SMEM = NST * STG; // 192KB

__global__ __launch_bounds__(256, 1) void gemm_tf32(const float* __restrict__ q,
                                                    const float* __restrict__ k,
                                                    const float* __restrict__ v) {
    extern __shared__ char smem[];
    const uint32_t sb = smem_u32(smem);
    const int tid = threadIdx.x;
    const int wid = tid >> 5;
    const int lane = tid & 31;
    const int z = blockIdx.z;

    const float* A = (z == 0) ? q : (z == 1) ? k : v;
    const float* B = g_wt[z];
    float* C = (z == 0) ? g_Qp : (z == 1) ? g_Kp : g_Vp;
    const size_t rowBase = (size_t)blockIdx.y * 128;
    const size_t colBase = (size_t)blockIdx.x * 256;

    // stage loader: A 128x64 fp32 + B 256x64 fp32; 16B segs, swizzled halves
    auto load_stage = [&](int chunk, int st) {
        const int k0 = chunk * 64;
        const uint32_t base = sb + st * STG;
#pragma unroll
        for (int j = 0; j < 8; j++) {
            int idx = tid + 256 * j;
            int r = idx >> 4, s = idx & 15;
            cp16(base + r * 256 + ((s >> 3) * 128) + (((s & 7) ^ (r & 7)) * 16),
                 A + (rowBase + r) * GK + k0 + s * 4);
        }
#pragma unroll
        for (int j = 0; j < 16; j++) {
            int idx = tid + 256 * j;
            int r = idx >> 4, s = idx & 15;
            cp16(base + 32768 + r * 256 + ((s >> 3) * 128) +
                     (((s & 7) ^ (r & 7)) * 16),
                 B + (colBase + r) * GK + k0 + s * 4);
        }
        cp_commit();
    };

    load_stage(0, 0);

    const int wm = wid >> 2;        // 0..1  (M)
    const int wn = wid & 3;         // 0..3  (N)
    const int g = lane >> 3;        // ldmatrix group
    const int lr = lane & 7;
    const int aRow = (g & 1) * 8 + lr;   // A row within 16
    const int aC = g >> 1;               // A seg select
    const int bRow = (g >> 1) * 8 + lr;  // B n-row within 16
    const int bC = g & 1;                // B seg select

    float acc[4][8][4];
#pragma unroll
    for (int i = 0; i < 4; i++)
#pragma unroll
        for (int j = 0; j < 8; j++)
#pragma unroll
            for (int p = 0; p < 4; p++) acc[i][j][p] = 0.f;

#pragma unroll 1
    for (int c = 0; c < 16; c++) {
        if (c + 1 < 16) {
            load_stage(c + 1, (c + 1) & 1);
            asm volatile("cp.async.wait_group 1;" ::: "memory");
        } else {
            asm volatile("cp.async.wait_group 0;" ::: "memory");
        }
        __syncthreads();

        const uint32_t AB = sb + (c & 1) * STG;
        const uint32_t BB = AB + 32768;

#pragma unroll
        for (int ks = 0; ks < 8; ks++) {
            uint32_t af[4][4];
#pragma unroll
            for (int mt = 0; mt < 4; mt++) {
                int row = wm * 64 + mt * 16 + aRow;
                int seg = 2 * ks + aC;
                ldx4(af[mt], AB + row * 256 + ((seg >> 3) * 128) +
                                 (((seg & 7) ^ lr) * 16));
#pragma unroll
                for (int p = 0; p < 4; p++) af[mt][p] = tf32r(af[mt][p]);
            }
            uint32_t bf[4][4];
#pragma unroll
            for (int pr = 0; pr < 4; pr++) {
                int row = wn * 64 + pr * 16 + bRow;
                int seg = 2 * ks + bC;
                ldx4(bf[pr], BB + row * 256 + ((seg >> 3) * 128) +
                                 (((seg & 7) ^ lr) * 16));
            }
#pragma unroll
            for (int mt = 0; mt < 4; mt++)
#pragma unroll
                for (int nt = 0; nt < 8; nt++)
                    mma_tf32(acc[mt][nt], af[mt], &bf[nt >> 1][(nt & 1) * 2]);
        }
        __syncthreads();   // protect stage (c&1) before iter c+1 overwrites (c+2)&1==(c&1)? no: c+1 loads (c+1)&1; c+2 loads (c&1): must be done reading
    }

    // epilogue: direct global stores
    const int tg = lane >> 2, tt = lane & 3;
#pragma unroll
    for (int mt = 0; mt < 4; mt++) {
#pragma unroll
        for (int nt = 0; nt < 8; nt++) {
            size_t row0 = rowBase + wm * 64 + mt * 16 + tg;
            size_t col = colBase + wn * 64 + nt * 8 + 2 * tt;
            *(float2*)(C + row0 * GN + col) =
                make_float2(acc[mt][nt][0], acc[mt][nt][1]);
            *(float2*)(C + (row0 + 8) * GN + col) =
                make_float2(acc[mt][nt][2], acc[mt][nt][3]);
        }
    }
}

// ------------- LayerNorm(K), LayerNorm(V), partial P = Kn^T Vn -------------
__global__ __launch_bounds__(256) void ln_pkv_kernel(const float* __restrict__ lnks,
                                                     const float* __restrict__ lnkb,
                                                     const float* __restrict__ lnvs,
                                                     const float* __restrict__ lnvb) {
    __shared__ float Ks[64][64];
    __shared__ float Vs[64][64];

    const int bh = blockIdx.y;
    const int chunk = blockIdx.x;
    const int h = bh & 15;

    const float* Kslab = g_Kp + (size_t)bh * (NSLAB * 64) + (size_t)chunk * 256 * 64;
    const float* Vslab = g_Vp + (size_t)bh * (NSLAB * 64) + (size_t)chunk * 256 * 64;

    const int tid = threadIdx.x;
    const int lane = tid & 31;
    const int warp = tid >> 5;
    const int tx = tid & 15;
    const int ty = tid >> 4;

    const float ks0 = lnks[h * 64 + 2 * lane], ks1 = lnks[h * 64 + 2 * lane + 1];
    const float kb0 = lnkb[h * 64 + 2 * lane], kb1 = lnkb[h * 64 + 2 * lane + 1];
    const float vs0 = lnvs[h * 64 + 2 * lane], vs1 = lnvs[h * 64 + 2 * lane + 1];
    const float vb0 = lnvb[h * 64 + 2 * lane], vb1 = lnvb[h * 64 + 2 * lane + 1];

    float acc[4][4];
#pragma unroll
    for (int i = 0; i < 4; i++)
#pragma unroll
        for (int j = 0; j < 4; j++) acc[i][j] = 0.f;

    for (int t = 0; t < 4; t++) {
#pragma unroll 1
        for (int rr = 0; rr < 8; rr++) {
            int r = warp * 8 + rr;
            int gr = t * 64 + r;
            {
                float2 kv = *(const float2*)(Kslab + (size_t)gr * 64 + 2 * lane);
                float s = kv.x + kv.y;
                float ss = kv.x * kv.x + kv.y * kv.y;
#pragma unroll
                for (int o = 16; o; o >>= 1) {
                    s  += __shfl_xor_sync(0xffffffffu, s, o);
                    ss += __shfl_xor_sync(0xffffffffu, ss, o);
                }
                float mean = s * (1.f / 64.f);
                float var = ss * (1.f / 64.f) - mean * mean;
                float rstd = rsqrtf(var + 1e-6f);
                Ks[r][2 * lane]     = (kv.x - mean) * rstd * ks0 + kb0;
                Ks[r][2 * lane + 1] = (kv.y - mean) * rstd * ks1 + kb1;
            }
            {
                float2 vv = *(const float2*)(Vslab + (size_t)gr * 64 + 2 * lane);
                float s = vv.x + vv.y;
                float ss = vv.x * vv.x + vv.y * vv.y;
#pragma unroll
                for (int o = 16; o; o >>= 1) {
                    s  += __shfl_xor_sync(0xffffffffu, s, o);
                    ss += __shfl_xor_sync(0xffffffffu, ss, o);
                }
                float mean = s * (1.f / 64.f);
                float var = ss * (1.f / 64.f) - mean * mean;
                float rstd = rsqrtf(var + 1e-6f);
                Vs[r][2 * lane]     = (vv.x - mean) * rstd * vs0 + vb0;
                Vs[r][2 * lane + 1] = (vv.y - mean) * rstd * vs1 + vb1;
            }
        }
        __syncthreads();
#pragma unroll 4
        for (int r = 0; r < 64; r++) {
            float4 a = *(const float4*)&Ks[r][ty * 4];
            float4 b = *(const float4*)&Vs[r][tx * 4];
            float av[4] = {a.x, a.y, a.z, a.w};
            float bv[4] = {b.x, b.y, b.z, b.w};
#pragma unroll
            for (int i = 0; i < 4; i++)
#pragma unroll
                for (int j = 0; j < 4; j++) acc[i][j] += av[i] * bv[j];
        }
        __syncthreads();
    }

    float* pp = g_Ppart + ((size_t)bh * NCHUNK + chunk) * 4096;
#pragma unroll
    for (int i = 0; i < 4; i++)
#pragma unroll
        for (int j = 0; j < 4; j++)
            pp[(ty * 4 + i) * 64 + tx * 4 + j] = acc[i][j];
}

// ------------- deterministic reduction of P partials -> d_out p_attn -------
__global__ __launch_bounds__(256) void preduce_kernel(float* __restrict__ out) {
    const int bh = blockIdx.x;
    const float* pp = g_Ppart + (size_t)bh * NCHUNK * 4096;
    float* po = out + ATT_SIZE + (size_t)bh * 4096;
    for (int idx = threadIdx.x; idx < 4096; idx += 256) {
        float s = 0.f;
#pragma unroll
        for (int c = 0; c < NCHUNK; c++) s += pp[(size_t)c * 4096 + idx];
        po[idx] = s * (1.f / (float)NSLAB);
    }
}

// ------------- x = Q_slab (8192x64) @ P (64x64), write att_output ----------
__global__ __launch_bounds__(256) void qp_kernel(float* __restrict__ out) {
    __shared__ float Ps[4096];
    __shared__ float Qs[64 * 68];

    const int bh = blockIdx.y;
    const int rc = blockIdx.x;

    const float* pin = out + ATT_SIZE + (size_t)bh * 4096;
    for (int i = threadIdx.x; i < 1024; i += 256)
        ((float4*)Ps)[i] = ((const float4*)pin)[i];

    const float* qsl = g_Qp + (size_t)bh * (NSLAB * 64) + (size_t)rc * 64 * 64;
    for (int i = threadIdx.x; i < 1024; i += 256) {
        float4 vv = ((const float4*)qsl)[i];
        int l = i * 4;
        int row = l >> 6;
        int col = l & 63;
        *(float4*)&Qs[row * 68 + col] = vv;
    }
    __syncthreads();

    const int row = threadIdx.x >> 2;
    const int c0 = (threadIdx.x & 3) * 16;

    float accv[16];
#pragma unroll
    for (int j = 0; j < 16; j++) accv[j] = 0.f;

#pragma unroll 8
    for (int d = 0; d < 64; d++) {
        float qv = Qs[row * 68 + d];
        float4 p0 = *(const float4*)&Ps[d * 64 + c0];
        float4 p1 = *(const float4*)&Ps[d * 64 + c0 + 4];
        float4 p2 = *(const float4*)&Ps[d * 64 + c0 + 8];
        float4 p3 = *(const float4*)&Ps[d * 64 + c0 + 12];
        accv[0] += qv * p0.x;  accv[1] += qv * p0.y;
        accv[2] += qv * p0.z;  accv[3] += qv * p0.w;
        accv[4] += qv * p1.x;  accv[5] += qv * p1.y;
        accv[6] += qv * p1.z;  accv[7] += qv * p1.w;
        accv[8] += qv * p2.x;  accv[9] += qv * p2.y;
        accv[10] += qv * p2.z; accv[11] += qv * p2.w;
        accv[12] += qv * p3.x; accv[13] += qv * p3.y;
        accv[14] += qv * p3.z; accv[15] += qv * p3.w;
    }

    float* orow = out + (size_t)bh * (NSLAB * 64) + (size_t)rc * 64 * 64 + row * 64 + c0;
    *(float4*)(orow + 0)  = make_float4(accv[0], accv[1], accv[2], accv[3]);
    *(float4*)(orow + 4)  = make_float4(accv[4], accv[5], accv[6], accv[7]);
    *(float4*)(orow + 8)  = make_float4(accv[8], accv[9], accv[10], accv[11]);
    *(float4*)(orow + 12) = make_float4(accv[12], accv[13], accv[14], accv[15]);
}

extern "C" void kernel_launch(void* const* d_in, const int* in_sizes, int n_in,
                              void* d_out, int out_size) {
    const float* query = (const float*)d_in[0];
    const float* key   = (const float*)d_in[1];
    const float* value = (const float*)d_in[2];
    const float* Wq    = (const float*)d_in[3];
    const float* Wk    = (const float*)d_in[4];
    const float* Wv    = (const float*)d_in[5];
    const float* lnks  = (const float*)d_in[6];
    const float* lnkb  = (const float*)d_in[7];
    const float* lnvs  = (const float*)d_in[8];
    const float* lnvb  = (const float*)d_in[9];
    float* out = (float*)d_out;

    cudaFuncSetAttribute(gemm_tf32, cudaFuncAttributeMaxDynamicSharedMemorySize,
                         GEMM_SMEM);

    convert_wT<<<dim3(32, 32, 3), 256>>>(Wq, Wk, Wv);   // launch 1
    pad_kernel<<<1, 32>>>();                            // launch 2
    pad_kernel<<<1, 32>>>();                            // launch 3
    gemm_tf32<<<dim3(GN / 256, GM / 128, 3), 256, GEMM_SMEM>>>(query, key, value); // 4
    ln_pkv_kernel<<<dim3(NCHUNK, NBH), 256>>>(lnks, lnkb, lnvs, lnvb);
    preduce_kernel<<<NBH, 256>>>(out);
    qp_kernel<<<dim3(NSLAB / 64, NBH), 256>>>(out);
}

// round 14
// speedup vs baseline: 2.5568x; 1.0495x over previous
#include <cuda_runtime.h>
#include <cuda_bf16.h>
#include <cstdint>

// Problem constants
constexpr int GM = 32768;          // B*S rows
constexpr int GK = 1024;           // F
constexpr int GN = 1024;           // F
constexpr int ATT_SIZE = 33554432; // B*S*F
constexpr int NBH = 64;            // B*H
constexpr int NSLAB = 8192;        // rows per head slab
constexpr int NCHUNK = 32;         // row chunks per slab for P accumulation

// -------------------- scratch (device globals; no allocs allowed) ----------
__device__ float g_Qp[(size_t)GM * GN];
__device__ float g_Kp[(size_t)GM * GN];
__device__ float g_Vp[(size_t)GM * GN];
__device__ float g_Ppart[(size_t)NBH * NCHUNK * 4096];
__device__ float g_wt[3][(size_t)GK * GN];   // W^T, tf32-rounded, [N][K]

// -------------------- PTX helpers (baseline sm_80 ISA) ---------------------
__device__ __forceinline__ uint32_t smem_u32(const void* p) {
    uint32_t a;
    asm("{ .reg .u64 t; cvta.to.shared.u64 t, %1; cvt.u32.u64 %0, t; }"
        : "=r"(a) : "l"(p));
    return a;
}
__device__ __forceinline__ void cp16(uint32_t dst, const void* src) {
    asm volatile("cp.async.cg.shared.global [%0], [%1], 16;"
                 :: "r"(dst), "l"(src) : "memory");
}
__device__ __forceinline__ void cp_commit() {
    asm volatile("cp.async.commit_group;" ::: "memory");
}
__device__ __forceinline__ void ldx4(uint32_t* r, uint32_t addr) {
    asm volatile("ldmatrix.sync.aligned.m8n8.x4.shared.b16 {%0,%1,%2,%3}, [%4];"
                 : "=r"(r[0]), "=r"(r[1]), "=r"(r[2]), "=r"(r[3]) : "r"(addr));
}
__device__ __forceinline__ uint32_t tf32r(uint32_t x) {
    uint32_t r;
    asm("cvt.rna.tf32.f32 %0, %1;" : "=r"(r) : "f"(__uint_as_float(x)));
    return r;
}
__device__ __forceinline__ void mma_tf32(float* c, const uint32_t* a,
                                         const uint32_t* b) {
    asm volatile(
        "mma.sync.aligned.m16n8k8.row.col.f32.tf32.tf32.f32 "
        "{%0,%1,%2,%3}, {%4,%5,%6,%7}, {%8,%9}, {%0,%1,%2,%3};"
        : "+f"(c[0]), "+f"(c[1]), "+f"(c[2]), "+f"(c[3])
        : "r"(a[0]), "r"(a[1]), "r"(a[2]), "r"(a[3]), "r"(b[0]), "r"(b[1]));
}

// -------------------- W transpose + tf32 round -----------------------------
__global__ __launch_bounds__(256) void convert_wT(const float* __restrict__ Wq,
                                                  const float* __restrict__ Wk,
                                                  const float* __restrict__ Wv) {
    const int z = blockIdx.z;
    const float* W = (z == 0 ? Wq : z == 1 ? Wk : Wv);
    __shared__ float t[32][33];
    const int tx = threadIdx.x & 31, ty = threadIdx.x >> 5;
    const int n0 = blockIdx.x * 32, k0 = blockIdx.y * 32;
#pragma unroll
    for (int j = 0; j < 32; j += 8)
        t[ty + j][tx] = W[(size_t)(k0 + ty + j) * GN + n0 + tx];
    __syncthreads();
#pragma unroll
    for (int j = 0; j < 32; j += 8) {
        uint32_t r = tf32r(__float_as_uint(t[tx][ty + j]));
        g_wt[z][(size_t)(n0 + ty + j) * GK + k0 + tx] = __uint_as_float(r);
    }
}

// tiny pad launches so ncu's captured launch index lands on gemm_tf32
__global__ void pad_kernel() {}

// -------------------- tf32 single-pass GEMM --------------------------------
// C(32768x1024) = A * W.  CTA tile 128x128, 128 threads (4 warps, 2Mx2N;
// warp tile 64x64).  BK=32 (fp32 rows = 128B = one swizzle atom), 3-stage
// cp.async pipeline, 32KB/stage -> 96KB smem/CTA -> 2 CTAs resident per SM
// so independent CTAs cover each other's barrier/startup bubbles.
constexpr int STG = 32768;            // A 16KB + B 16KB per stage
constexpr int NST = 3;
constexpr int GEMM_SMEM = NST * STG;  // 96KB
constexpr int NCHK = GK / 32;         // 32 k-chunks

__global__ __launch_bounds__(128, 2) void gemm_tf32(const float* __restrict__ q,
                                                    const float* __restrict__ k,
                                                    const float* __restrict__ v) {
    extern __shared__ char smem[];
    const uint32_t sb = smem_u32(smem);
    const int tid = threadIdx.x;
    const int wid = tid >> 5;
    const int lane = tid & 31;
    const int z = blockIdx.z;

    const float* A = (z == 0) ? q : (z == 1) ? k : v;
    const float* B = g_wt[z];
    float* C = (z == 0) ? g_Qp : (z == 1) ? g_Kp : g_Vp;
    const size_t rowBase = (size_t)blockIdx.y * 128;
    const size_t colBase = (size_t)blockIdx.x * 128;

    // stage loader: A 128x32 fp32 + B 128x32 fp32; 16B segs, swizzled rows
    auto load_stage = [&](int chunk, int st) {
        const int k0 = chunk * 32;
        const uint32_t base = sb + st * STG;
#pragma unroll
        for (int j = 0; j < 8; j++) {
            int idx = tid + 128 * j;
            int r = idx >> 3, s = idx & 7;
            cp16(base + r * 128 + ((s ^ (r & 7)) * 16),
                 A + (rowBase + r) * GK + k0 + s * 4);
        }
#pragma unroll
        for (int j = 0; j < 8; j++) {
            int idx = tid + 128 * j;
            int r = idx >> 3, s = idx & 7;
            cp16(base + 16384 + r * 128 + ((s ^ (r & 7)) * 16),
                 B + (colBase + r) * GK + k0 + s * 4);
        }
        cp_commit();
    };

    load_stage(0, 0);
    load_stage(1, 1);

    const int wm = wid >> 1;        // 0..1  (M)
    const int wn = wid & 1;         // 0..1  (N)
    const int g = lane >> 3;        // ldmatrix group
    const int lr = lane & 7;
    const int aRow = (g & 1) * 8 + lr;   // A row within 16
    const int aC = g >> 1;               // A seg select
    const int bRow = (g >> 1) * 8 + lr;  // B n-row within 16
    const int bC = g & 1;                // B seg select

    float acc[4][8][4];
#pragma unroll
    for (int i = 0; i < 4; i++)
#pragma unroll
        for (int j = 0; j < 8; j++)
#pragma unroll
            for (int p = 0; p < 4; p++) acc[i][j][p] = 0.f;

#pragma unroll 1
    for (int c = 0; c < NCHK; c++) {
        if (c < NCHK - 1) {
            asm volatile("cp.async.wait_group 1;" ::: "memory");
        } else {
            asm volatile("cp.async.wait_group 0;" ::: "memory");
        }
        __syncthreads();
        if (c + 2 < NCHK) load_stage(c + 2, (c + 2) % 3);

        const uint32_t AB = sb + (c % 3) * STG;
        const uint32_t BB = AB + 16384;

#pragma unroll
        for (int ks = 0; ks < 4; ks++) {
            uint32_t af[4][4];
#pragma unroll
            for (int mt = 0; mt < 4; mt++) {
                int row = wm * 64 + mt * 16 + aRow;
                int seg = 2 * ks + aC;
                ldx4(af[mt], AB + row * 128 + ((seg ^ lr) * 16));
#pragma unroll
                for (int p = 0; p < 4; p++) af[mt][p] = tf32r(af[mt][p]);
            }
            uint32_t bf[4][4];
#pragma unroll
            for (int pr = 0; pr < 4; pr++) {
                int row = wn * 64 + pr * 16 + bRow;
                int seg = 2 * ks + bC;
                ldx4(bf[pr], BB + row * 128 + ((seg ^ lr) * 16));
            }
#pragma unroll
            for (int mt = 0; mt < 4; mt++)
#pragma unroll
                for (int nt = 0; nt < 8; nt++)
                    mma_tf32(acc[mt][nt], af[mt], &bf[nt >> 1][(nt & 1) * 2]);
        }
    }

    // epilogue: direct global stores
    const int tg = lane >> 2, tt = lane & 3;
#pragma unroll
    for (int mt = 0; mt < 4; mt++) {
#pragma unroll
        for (int nt = 0; nt < 8; nt++) {
            size_t row0 = rowBase + wm * 64 + mt * 16 + tg;
            size_t col = colBase + wn * 64 + nt * 8 + 2 * tt;
            *(float2*)(C + row0 * GN + col) =
                make_float2(acc[mt][nt][0], acc[mt][nt][1]);
            *(float2*)(C + (row0 + 8) * GN + col) =
                make_float2(acc[mt][nt][2], acc[mt][nt][3]);
        }
    }
}

// ------------- LayerNorm(K), LayerNorm(V), partial P = Kn^T Vn -------------
__global__ __launch_bounds__(256) void ln_pkv_kernel(const float* __restrict__ lnks,
                                                     const float* __restrict__ lnkb,
                                                     const float* __restrict__ lnvs,
                                                     const float* __restrict__ lnvb) {
    __shared__ float Ks[64][64];
    __shared__ float Vs[64][64];

    const int bh = blockIdx.y;
    const int chunk = blockIdx.x;
    const int h = bh & 15;

    const float* Kslab = g_Kp + (size_t)bh * (NSLAB * 64) + (size_t)chunk * 256 * 64;
    const float* Vslab = g_Vp + (size_t)bh * (NSLAB * 64) + (size_t)chunk * 256 * 64;

    const int tid = threadIdx.x;
    const int lane = tid & 31;
    const int warp = tid >> 5;
    const int tx = tid & 15;
    const int ty = tid >> 4;

    const float ks0 = lnks[h * 64 + 2 * lane], ks1 = lnks[h * 64 + 2 * lane + 1];
    const float kb0 = lnkb[h * 64 + 2 * lane], kb1 = lnkb[h * 64 + 2 * lane + 1];
    const float vs0 = lnvs[h * 64 + 2 * lane], vs1 = lnvs[h * 64 + 2 * lane + 1];
    const float vb0 = lnvb[h * 64 + 2 * lane], vb1 = lnvb[h * 64 + 2 * lane + 1];

    float acc[4][4];
#pragma unroll
    for (int i = 0; i < 4; i++)
#pragma unroll
        for (int j = 0; j < 4; j++) acc[i][j] = 0.f;

    for (int t = 0; t < 4; t++) {
#pragma unroll 1
        for (int rr = 0; rr < 8; rr++) {
            int r = warp * 8 + rr;
            int gr = t * 64 + r;
            {
                float2 kv = *(const float2*)(Kslab + (size_t)gr * 64 + 2 * lane);
                float s = kv.x + kv.y;
                float ss = kv.x * kv.x + kv.y * kv.y;
#pragma unroll
                for (int o = 16; o; o >>= 1) {
                    s  += __shfl_xor_sync(0xffffffffu, s, o);
                    ss += __shfl_xor_sync(0xffffffffu, ss, o);
                }
                float mean = s * (1.f / 64.f);
                float var = ss * (1.f / 64.f) - mean * mean;
                float rstd = rsqrtf(var + 1e-6f);
                Ks[r][2 * lane]     = (kv.x - mean) * rstd * ks0 + kb0;
                Ks[r][2 * lane + 1] = (kv.y - mean) * rstd * ks1 + kb1;
            }
            {
                float2 vv = *(const float2*)(Vslab + (size_t)gr * 64 + 2 * lane);
                float s = vv.x + vv.y;
                float ss = vv.x * vv.x + vv.y * vv.y;
#pragma unroll
                for (int o = 16; o; o >>= 1) {
                    s  += __shfl_xor_sync(0xffffffffu, s, o);
                    ss += __shfl_xor_sync(0xffffffffu, ss, o);
                }
                float mean = s * (1.f / 64.f);
                float var = ss * (1.f / 64.f) - mean * mean;
                float rstd = rsqrtf(var + 1e-6f);
                Vs[r][2 * lane]     = (vv.x - mean) * rstd * vs0 + vb0;
                Vs[r][2 * lane + 1] = (vv.y - mean) * rstd * vs1 + vb1;
            }
        }
        __syncthreads();
#pragma unroll 4
        for (int r = 0; r < 64; r++) {
            float4 a = *(const float4*)&Ks[r][ty * 4];
            float4 b = *(const float4*)&Vs[r][tx * 4];
            float av[4] = {a.x, a.y, a.z, a.w};
            float bv[4] = {b.x, b.y, b.z, b.w};
#pragma unroll
            for (int i = 0; i < 4; i++)
#pragma unroll
                for (int j = 0; j < 4; j++) acc[i][j] += av[i] * bv[j];
        }
        __syncthreads();
    }

    float* pp = g_Ppart + ((size_t)bh * NCHUNK + chunk) * 4096;
#pragma unroll
    for (int i = 0; i < 4; i++)
#pragma unroll
        for (int j = 0; j < 4; j++)
            pp[(ty * 4 + i) * 64 + tx * 4 + j] = acc[i][j];
}

// ------------- deterministic reduction of P partials -> d_out p_attn -------
__global__ __launch_bounds__(256) void preduce_kernel(float* __restrict__ out) {
    const int bh = blockIdx.x;
    const float* pp = g_Ppart + (size_t)bh * NCHUNK * 4096;
    float* po = out + ATT_SIZE + (size_t)bh * 4096;
    for (int idx = threadIdx.x; idx < 4096; idx += 256) {
        float s = 0.f;
#pragma unroll
        for (int c = 0; c < NCHUNK; c++) s += pp[(size_t)c * 4096 + idx];
        po[idx] = s * (1.f / (float)NSLAB);
    }
}

// ------------- x = Q_slab (8192x64) @ P (64x64), write att_output ----------
__global__ __launch_bounds__(256) void qp_kernel(float* __restrict__ out) {
    __shared__ float Ps[4096];
    __shared__ float Qs[64 * 68];

    const int bh = blockIdx.y;
    const int rc = blockIdx.x;

    const float* pin = out + ATT_SIZE + (size_t)bh * 4096;
    for (int i = threadIdx.x; i < 1024; i += 256)
        ((float4*)Ps)[i] = ((const float4*)pin)[i];

    const float* qsl = g_Qp + (size_t)bh * (NSLAB * 64) + (size_t)rc * 64 * 64;
    for (int i = threadIdx.x; i < 1024; i += 256) {
        float4 vv = ((const float4*)qsl)[i];
        int l = i * 4;
        int row = l >> 6;
        int col = l & 63;
        *(float4*)&Qs[row * 68 + col] = vv;
    }
    __syncthreads();

    const int row = threadIdx.x >> 2;
    const int c0 = (threadIdx.x & 3) * 16;

    float accv[16];
#pragma unroll
    for (int j = 0; j < 16; j++) accv[j] = 0.f;

#pragma unroll 8
    for (int d = 0; d < 64; d++) {
        float qv = Qs[row * 68 + d];
        float4 p0 = *(const float4*)&Ps[d * 64 + c0];
        float4 p1 = *(const float4*)&Ps[d * 64 + c0 + 4];
        float4 p2 = *(const float4*)&Ps[d * 64 + c0 + 8];
        float4 p3 = *(const float4*)&Ps[d * 64 + c0 + 12];
        accv[0] += qv * p0.x;  accv[1] += qv * p0.y;
        accv[2] += qv * p0.z;  accv[3] += qv * p0.w;
        accv[4] += qv * p1.x;  accv[5] += qv * p1.y;
        accv[6] += qv * p1.z;  accv[7] += qv * p1.w;
        accv[8] += qv * p2.x;  accv[9] += qv * p2.y;
        accv[10] += qv * p2.z; accv[11] += qv * p2.w;
        accv[12] += qv * p3.x; accv[13] += qv * p3.y;
        accv[14] += qv * p3.z; accv[15] += qv * p3.w;
    }

    float* orow = out + (size_t)bh * (NSLAB * 64) + (size_t)rc * 64 * 64 + row * 64 + c0;
    *(float4*)(orow + 0)  = make_float4(accv[0], accv[1], accv[2], accv[3]);
    *(float4*)(orow + 4)  = make_float4(accv[4], accv[5], accv[6], accv[7]);
    *(float4*)(orow + 8)  = make_float4(accv[8], accv[9], accv[10], accv[11]);
    *(float4*)(orow + 12) = make_float4(accv[12], accv[13], accv[14], accv[15]);
}

extern "C" void kernel_launch(void* const* d_in, const int* in_sizes, int n_in,
                              void* d_out, int out_size) {
    const float* query = (const float*)d_in[0];
    const float* key   = (const float*)d_in[1];
    const float* value = (const float*)d_in[2];
    const float* Wq    = (const float*)d_in[3];
    const float* Wk    = (const float*)d_in[4];
    const float* Wv    = (const float*)d_in[5];
    const float* lnks  = (const float*)d_in[6];
    const float* lnkb  = (const float*)d_in[7];
    const float* lnvs  = (const float*)d_in[8];
    const float* lnvb  = (const float*)d_in[9];
    float* out = (float*)d_out;

    cudaFuncSetAttribute(gemm_tf32, cudaFuncAttributeMaxDynamicSharedMemorySize,
                         GEMM_SMEM);

    convert_wT<<<dim3(32, 32, 3), 256>>>(Wq, Wk, Wv);   // launch 1
    pad_kernel<<<1, 32>>>();                            // launch 2
    pad_kernel<<<1, 32>>>();                            // launch 3
    gemm_tf32<<<dim3(GN / 128, GM / 128, 3), 128, GEMM_SMEM>>>(query, key, value); // 4
    ln_pkv_kernel<<<dim3(NCHUNK, NBH), 256>>>(lnks, lnkb, lnvs, lnvb);
    preduce_kernel<<<NBH, 256>>>(out);
    qp_kernel<<<dim3(NSLAB / 64, NBH), 256>>>(out);
}